// round 17
// baseline (speedup 1.0000x reference)
#include <cuda_runtime.h>
#include <cuda_fp16.h>
#include <cstdint>

#define Bn  32
#define ICn 512
#define OCn 512

// ---------------- device scratch (no allocation allowed) ----------------
__device__ float g_style[Bn * ICn];
__device__ float g_demod[Bn * OCn];
__device__ float g_wsqT[ICn * OCn];          // [ic][oc]
__device__ float g_lwT[512 * 512];           // lin_w transposed [k][i]
// weights fp16, c1 applied, ksig2-permuted rows: [72 chunks][512 oc][64 k]
__device__ __align__(16) __half g_mw[72 * 512 * 64];
// modulated input fp16, channel-last, ksig2-permuted per 64-group
__device__ __align__(16) __half g_xh[(size_t)Bn * 4096 * 512];

// ksig2: storage position (halfs) of logical k within a 64-k row:
// pos = tg*16 + ks*4 + intra
__host__ __device__ __forceinline__ int ksig2(int k) {
    return ((k >> 1) & 3) * 16 + ((k >> 4) & 3) * 4 + ((k >> 3) & 1) * 2 + (k & 1);
}

// ---------------- prep0: lin_w transpose + weight tiles + wsqT ----------------
__global__ void prep0_kernel(const float* __restrict__ lin_w, const float* __restrict__ conv_w) {
    __shared__ float sm[1152];
    int blk = blockIdx.x, tid = threadIdx.x;       // 256 threads
    int tx = tid & 31, ty = tid >> 5;              // 32 x 8
    if (blk < 256) {
        int i0 = (blk >> 4) * 32, k0 = (blk & 15) * 32;
#pragma unroll
        for (int u = 0; u < 4; u++)
            sm[(ty + 8 * u) * 33 + tx] = lin_w[(size_t)(i0 + ty + 8 * u) * 512 + k0 + tx];
        __syncthreads();
#pragma unroll
        for (int u = 0; u < 4; u++)
            g_lwT[(size_t)(k0 + ty + 8 * u) * 512 + i0 + tx] = sm[tx * 33 + ty + 8 * u];
    } else {
        int bi = blk - 256;                // 2048 blocks: one (oc, ic-quarter) each
        int oc = bi >> 2, q = bi & 3;
        const float* src = conv_w + (size_t)oc * 4608 + q * 1152;
        for (int i = tid; i < 1152; i += 256) sm[i] = src[i];
        __syncthreads();
        if (tid < 128) {
            int icl = tid;
            float sq = 0.f;
#pragma unroll
            for (int t = 0; t < 9; t++) { float v = sm[icl * 9 + t]; sq += v * v; }
            g_wsqT[(size_t)(q * 128 + icl) * 512 + oc] = sq;
        }
        if (tid < 72) {
            int g = tid;
            int chunk_l = g >> 2, kg = g & 3;      // chunk_l = icb_l*9 + tap
            int icb_l = chunk_l / 9, tap = chunk_l - icb_l * 9;
            int chunk = (2 * q + icb_l) * 9 + tap;
#pragma unroll
            for (int t = 0; t < 4; t++) {
                int base = icb_l * 64 + kg * 16 + 2 * t;
                __half h[4];
                h[0] = __float2half_rn(sm[(base)     * 9 + tap] * (1.0f / 48.0f));
                h[1] = __float2half_rn(sm[(base + 1) * 9 + tap] * (1.0f / 48.0f));
                h[2] = __float2half_rn(sm[(base + 8) * 9 + tap] * (1.0f / 48.0f));
                h[3] = __float2half_rn(sm[(base + 9) * 9 + tap] * (1.0f / 48.0f));
                *(uint2*)(g_mw + (size_t)chunk * 32768 + oc * 64 + t * 16 + kg * 4)
                    = *(uint2*)h;
            }
        }
    }
}

// ---------------- prep1: style MLP (coalesced via g_lwT) ----------------
__global__ void prep1_kernel(const float* __restrict__ w, const float* __restrict__ lin_b) {
    __shared__ float wv[512];
    int b = blockIdx.x, tid = threadIdx.x;         // 32 blocks x 256
    wv[tid] = w[b * 512 + tid];
    wv[tid + 256] = w[b * 512 + tid + 256];
    __syncthreads();
#pragma unroll
    for (int h = 0; h < 2; h++) {
        int i = tid + h * 256;
        float acc = 0.f;
#pragma unroll 8
        for (int k = 0; k < 512; k++) acc += wv[k] * g_lwT[(size_t)k * 512 + i];
        g_style[b * 512 + i] = acc * (1.0f / 16.0f) + lin_b[i];
    }
}

// ---------------- prep2: demod (coalesced) + xmod ----------------
__global__ void prep2_kernel(const float* __restrict__ x) {
    int tx = threadIdx.x, ty = threadIdx.y;        // 32 x 8
    int t = ty * 32 + tx;
    if (blockIdx.x < 32) {
        __shared__ float s2[512];
        int b = blockIdx.x;
        float sv0 = g_style[b * 512 + t], sv1 = g_style[b * 512 + t + 256];
        s2[t] = sv0 * sv0; s2[t + 256] = sv1 * sv1;
        __syncthreads();
#pragma unroll
        for (int h = 0; h < 2; h++) {
            int o = t + h * 256;
            float acc = 0.f;
#pragma unroll 8
            for (int i = 0; i < 512; i++) acc += s2[i] * g_wsqT[(size_t)i * 512 + o];
            g_demod[b * 512 + o] = rsqrtf(acc * (1.0f / 2304.0f) + 1e-8f);
        }
    } else {
        __shared__ float tb[32][33];
        int r = blockIdx.x - 32;
        int b = r >> 11;
        int rr = r & 2047;
        int yx0 = (rr >> 4) * 32, ic0 = (rr & 15) * 32;
#pragma unroll
        for (int k = 0; k < 4; k++)
            tb[ty + 8 * k][tx] = x[((size_t)(b * 512 + ic0 + ty + 8 * k) << 12) + yx0 + tx];
        __syncthreads();
#pragma unroll
        for (int k = 0; k < 4; k++) {
            int yx = yx0 + ty + 8 * k;
            int ic = ic0 + tx;
            float v = tb[tx][ty + 8 * k] * g_style[b * 512 + ic];
            int ics = (ic & ~63) | ksig2(ic & 63);
            g_xh[(((size_t)b << 12) + yx) * 512 + ics] = __float2half_rn(v);
        }
    }
}

// ---------------- main conv: double-buffered patch, 3-ring B, global chunk loop ----------------
#define MMA16816(d, a, b0_, b1_) \
    asm volatile("mma.sync.aligned.m16n8k16.row.col.f32.f16.f16.f32 " \
        "{%0,%1,%2,%3}, {%4,%5,%6,%7}, {%8,%9}, {%0,%1,%2,%3};" \
        : "+f"((d)[0]), "+f"((d)[1]), "+f"((d)[2]), "+f"((d)[3]) \
        : "r"((a)[0]), "r"((a)[1]), "r"((a)[2]), "r"((a)[3]), "r"(b0_), "r"(b1_))

#define CP16(dst, src, sz) \
    asm volatile("cp.async.cg.shared.global [%0], [%1], 16, %2;" \
                 :: "r"(dst), "l"(src), "r"(sz) : "memory")
#define CP_COMMIT() asm volatile("cp.async.commit_group;" ::: "memory")
#define CP_WAIT(n)  asm volatile("cp.async.wait_group %0;" :: "n"(n) : "memory")

#define PSTB 128                 // dense rows: 64 fp16
#define PATCH_SZ 26112           // 204 * 128
#define BB_SZ 16384              // 128 * 128
#define P0_OFF 0
#define P1_OFF 26112
#define B0_OFF 52224
#define SMEM_CONV (52224 + 3 * 16384)   // 101376

__device__ __forceinline__ uint32_t smem_u32(const void* p) {
    uint32_t a;
    asm("{ .reg .u64 t; cvta.to.shared.u64 t, %1; cvt.u32.u64 %0, t; }" : "=r"(a) : "l"(p));
    return a;
}
__device__ __forceinline__ uint4 lds128(const char* p) {
    return *(const uint4*)p;
}

__global__ void __launch_bounds__(256, 2) conv_kernel(
    const float* __restrict__ noise, const float* __restrict__ bias,
    const float* __restrict__ noise_w, float* __restrict__ out)
{
    extern __shared__ __align__(16) char smem[];
    const uint32_t uS = smem_u32(smem);

    const int tid  = threadIdx.x;
    const int lane = tid & 31, wid = tid >> 5;
    const int b   = blockIdx.z;
    const int oc0 = blockIdx.y * 128;
    const int mt  = blockIdx.x;
    const int y0  = (mt >> 1) * 4;                // 4 rows x 32 cols output tile
    const int x0  = (mt & 1) * 32;

    const int wm = wid >> 1, wn = wid & 1;        // warp tile 32m x 64n
    const int gr = lane >> 2, tg = lane & 3;

    float acc[2][8][4];
#pragma unroll
    for (int mi = 0; mi < 2; mi++)
#pragma unroll
        for (int ni = 0; ni < 8; ni++)
#pragma unroll
            for (int r = 0; r < 4; r++) acc[mi][ni][r] = 0.f;

    // ---- hoisted per-thread constants ----
    const int m0base = wm * 32;
    int pixA[2], pixB[2];                         // patch pixel-base byte offsets
#pragma unroll
    for (int mi = 0; mi < 2; mi++) {
        int ma = m0base + mi * 16 + gr, mb = ma + 8;
        pixA[mi] = (((ma >> 5) * 34) + (ma & 31)) * PSTB;
        pixB[mi] = (((mb >> 5) * 34) + (mb & 31)) * PSTB;
    }
    const int fragoff = tg * 32;                  // within-row byte offset base
    const int brow0 = (wn * 64 + gr) * PSTB + fragoff;

    // patch-fill role constants (2 units/thread, each 64B = 4 cp.async)
    int pu_dst[2]; size_t pu_src[2]; uint32_t pu_sz[2];
#pragma unroll
    for (int q = 0; q < 2; q++) {
        int u = tid + q * 256;
        if (u < 408) {
            int pp = u >> 1, hf = u & 1;
            int pr = pp / 34, pc = pp - pr * 34;
            int gy = y0 + pr - 1, gx = x0 + pc - 1;
            bool ok = ((unsigned)gy < 64u) && ((unsigned)gx < 64u);
            pu_sz[q] = ok ? 16u : 0u;
            pu_src[q] = ok ? ((((size_t)b << 12) + gy * 64 + gx) * 512 + hf * 32) : 0;
            pu_dst[q] = pp * PSTB + hf * 64;
        } else { pu_sz[q] = 0; pu_src[q] = 0; pu_dst[q] = -1; }
    }

    // ---- prologue: patch(icb=0) + B(chunk 0), rigorous wait+barrier ----
#pragma unroll
    for (int q = 0; q < 2; q++) {
        if (pu_dst[q] >= 0) {
            const char* sh = (const char*)(g_xh + pu_src[q]);
            uint32_t dh = uS + P0_OFF + pu_dst[q];
#pragma unroll
            for (int s = 0; s < 4; s++) CP16(dh + s * 16, sh + s * 16, pu_sz[q]);
        }
    }
    {
        const char* src = (const char*)(g_mw + ((size_t)0 * 512 + oc0) * 64);
#pragma unroll
        for (int q = 0; q < 4; q++) {
            int u = q * 256 + tid;
            CP16(uS + B0_OFF + u * 16, src + u * 16, 16u);
        }
    }
    CP_COMMIT();
    CP_WAIT(0);
    __syncthreads();

    for (int icb = 0; icb < 8; icb++) {
        const char* pH = smem + ((icb & 1) ? P1_OFF : P0_OFF);
        for (int tap = 0; tap < 9; tap++) {
            const int c = icb * 9 + tap;
            if (c && !(tap & 1)) __syncthreads();      // WAR: ring/patch reuse
            // B prefetch, distance 1 (rolls across icb boundaries)
            if (c < 71) {
                const char* src = (const char*)(g_mw + ((size_t)(c + 1) * 512 + oc0) * 64);
                uint32_t dB = uS + B0_OFF + ((c + 1) % 3) * BB_SZ;
#pragma unroll
                for (int q = 0; q < 4; q++) {
                    int u = q * 256 + tid;
                    CP16(dB + u * 16, src + u * 16, 16u);
                }
                CP_COMMIT();
            }
            // patch prefetch for icb+1 at tap 4
            if (tap == 4 && icb < 7) {
                uint32_t pbase = uS + ((icb & 1) ? P0_OFF : P1_OFF);
                size_t icoff = (size_t)(icb + 1) * 64;
#pragma unroll
                for (int q = 0; q < 2; q++) {
                    if (pu_dst[q] >= 0) {
                        const char* sh = (const char*)(g_xh + pu_src[q] + icoff);
                        uint32_t dh = pbase + pu_dst[q];
#pragma unroll
                        for (int s = 0; s < 4; s++) CP16(dh + s * 16, sh + s * 16, pu_sz[q]);
                    }
                }
                CP_COMMIT();
            }
            // wait ledger: B(c) must be done; patch group allowed at taps 4-5
            if (c == 71)                       { CP_WAIT(0); }
            else if ((tap == 4 || tap == 5) && icb < 7) { CP_WAIT(2); }
            else                               { CP_WAIT(1); }

            const int toff = (tap / 3) * (34 * PSTB) + (tap % 3) * PSTB;
            const char* bbase = smem + B0_OFF + (c % 3) * BB_SZ;

#pragma unroll
            for (int pair = 0; pair < 2; pair++) {
                const int off = fragoff + pair * 16;
                uint4 bq[8];
#pragma unroll
                for (int ni = 0; ni < 8; ni++)
                    bq[ni] = lds128(bbase + brow0 + ni * (8 * PSTB) + pair * 16);
#pragma unroll
                for (int mi = 0; mi < 2; mi++) {
                    uint4 Aa = lds128(pH + pixA[mi] + toff + off);
                    uint4 Ab = lds128(pH + pixB[mi] + toff + off);
                    uint32_t ah0[4] = { Aa.x, Ab.x, Aa.y, Ab.y };
                    uint32_t ah1[4] = { Aa.z, Ab.z, Aa.w, Ab.w };
#pragma unroll
                    for (int ni = 0; ni < 8; ni++) {
                        MMA16816(acc[mi][ni], ah0, bq[ni].x, bq[ni].y);
                        MMA16816(acc[mi][ni], ah1, bq[ni].z, bq[ni].w);
                    }
                }
            }
        }
    }

    // ---- epilogue: demod + bias + noise ----
#pragma unroll
    for (int mi = 0; mi < 2; mi++)
#pragma unroll
        for (int ni = 0; ni < 8; ni++) {
            int oc = oc0 + wn * 64 + ni * 8 + tg * 2;
            int m  = m0base + mi * 16 + gr;
            float dm0 = g_demod[b * 512 + oc],  dm1 = g_demod[b * 512 + oc + 1];
            float bs0 = bias[oc],               bs1 = bias[oc + 1];
            float nw0 = noise_w[oc],            nw1 = noise_w[oc + 1];
#pragma unroll
            for (int rr = 0; rr < 2; rr++) {
                int mm = m + rr * 8;
                int yy = y0 + (mm >> 5), xx = x0 + (mm & 31);
                size_t i0 = ((size_t)(b * 512 + oc) << 12) + yy * 64 + xx;
                size_t i1 = i0 + 4096;
                out[i0] = acc[mi][ni][rr * 2 + 0] * dm0 + bs0 + nw0 * noise[i0];
                out[i1] = acc[mi][ni][rr * 2 + 1] * dm1 + bs1 + nw1 * noise[i1];
            }
        }
}

// ---------------------------------------------------------------------------
// Inputs (metadata order): x, w, conv_w, lin_w, lin_b, bias, noise_w, noise
// ---------------------------------------------------------------------------
extern "C" void kernel_launch(void* const* d_in, const int* in_sizes, int n_in,
                              void* d_out, int out_size) {
    (void)in_sizes; (void)n_in; (void)out_size;
    const float* x       = (const float*)d_in[0];
    const float* w       = (const float*)d_in[1];
    const float* conv_w  = (const float*)d_in[2];
    const float* lin_w   = (const float*)d_in[3];
    const float* lin_b   = (const float*)d_in[4];
    const float* bias    = (const float*)d_in[5];
    const float* noise_w = (const float*)d_in[6];
    const float* noise   = (const float*)d_in[7];
    float* out = (float*)d_out;

    cudaFuncSetAttribute(conv_kernel, cudaFuncAttributeMaxDynamicSharedMemorySize, SMEM_CONV);

    prep0_kernel<<<256 + 2048, 256>>>(lin_w, conv_w);
    prep1_kernel<<<32, 256>>>(w, lin_b);
    {
        dim3 t(32, 8);
        prep2_kernel<<<32 + Bn * 128 * 16, t>>>(x);
    }
    {
        dim3 grid(32, 4, Bn);
        conv_kernel<<<grid, 256, SMEM_CONV>>>(noise, bias, noise_w, out);
    }
}